// round 1
// baseline (speedup 1.0000x reference)
#include <cuda_runtime.h>

#define Bsz 4
#define Seq 2048
#define Dm  1024
#define Hn  16
#define Hd  64
#define Mrows (Bsz*Seq)   // 8192

// Scratch (allocation-free rule: __device__ globals)
__device__ float g_q[Bsz*Hn*Seq*Hd];     // [B,H,S,HD]
__device__ float g_k[Bsz*Hn*Seq*Hd];
__device__ float g_v[Bsz*Hn*Seq*Hd];
__device__ float g_att[Bsz*Seq*Dm];      // [B,S,D] (D = h*64+hd)

// ---------------------------------------------------------------------------
// 128x128x8 fp32 GEMM tile core: C = X[M,K] @ W[N,K]^T   (both K-major)
// 256 threads, 8x8 per-thread register tile, register prefetch.
// ---------------------------------------------------------------------------
__device__ __forceinline__ void gemm_tile_128(const float* __restrict__ X,
                                              const float* __restrict__ W,
                                              int K, int row0, int col0,
                                              float acc[8][8])
{
    __shared__ float As[8][128];   // As[k][m]
    __shared__ float Bs[8][128];   // Bs[k][n]

    const int tid  = threadIdx.x;
    const int tx   = tid & 15;
    const int ty   = tid >> 4;
    const int lrow = tid >> 1;            // 0..127
    const int lseg = (tid & 1) * 4;       // 0 or 4

    const float* xptr = X + (size_t)(row0 + lrow) * K + lseg;
    const float* wptr = W + (size_t)(col0 + lrow) * K + lseg;

    float4 xa = *(const float4*)(xptr);
    float4 wb = *(const float4*)(wptr);

    for (int k0 = 0; k0 < K; k0 += 8) {
        __syncthreads();
        As[lseg+0][lrow] = xa.x; As[lseg+1][lrow] = xa.y;
        As[lseg+2][lrow] = xa.z; As[lseg+3][lrow] = xa.w;
        Bs[lseg+0][lrow] = wb.x; Bs[lseg+1][lrow] = wb.y;
        Bs[lseg+2][lrow] = wb.z; Bs[lseg+3][lrow] = wb.w;
        __syncthreads();

        if (k0 + 8 < K) {
            xa = *(const float4*)(xptr + k0 + 8);
            wb = *(const float4*)(wptr + k0 + 8);
        }

        #pragma unroll
        for (int k = 0; k < 8; k++) {
            float4 a0 = *(const float4*)&As[k][ty*8];
            float4 a1 = *(const float4*)&As[k][ty*8+4];
            float4 b0 = *(const float4*)&Bs[k][tx*8];
            float4 b1 = *(const float4*)&Bs[k][tx*8+4];
            float av[8] = {a0.x,a0.y,a0.z,a0.w,a1.x,a1.y,a1.z,a1.w};
            float bv[8] = {b0.x,b0.y,b0.z,b0.w,b1.x,b1.y,b1.z,b1.w};
            #pragma unroll
            for (int i = 0; i < 8; i++)
                #pragma unroll
                for (int j = 0; j < 8; j++)
                    acc[i][j] += av[i] * bv[j];
        }
    }
}

// ---------------------------------------------------------------------------
// QKV projection: grid.z selects {Q,K,V}; writes [B,H,S,HD] layout
// ---------------------------------------------------------------------------
__global__ __launch_bounds__(256)
void qkv_kernel(const float* __restrict__ X,
                const float* __restrict__ Wq, const float* __restrict__ bq,
                const float* __restrict__ Wk, const float* __restrict__ bk,
                const float* __restrict__ Wv, const float* __restrict__ bv)
{
    const float *W, *bias;
    float* out;
    if (blockIdx.z == 0)      { W = Wq; bias = bq; out = g_q; }
    else if (blockIdx.z == 1) { W = Wk; bias = bk; out = g_k; }
    else                      { W = Wv; bias = bv; out = g_v; }

    float acc[8][8];
    #pragma unroll
    for (int i = 0; i < 8; i++)
        #pragma unroll
        for (int j = 0; j < 8; j++) acc[i][j] = 0.f;

    const int row0 = blockIdx.y * 128;
    const int col0 = blockIdx.x * 128;
    gemm_tile_128(X, W, Dm, row0, col0, acc);

    const int tx = threadIdx.x & 15, ty = threadIdx.x >> 4;
    const int cbase = col0 + tx * 8;
    const float4 bb0 = *(const float4*)&bias[cbase];
    const float4 bb1 = *(const float4*)&bias[cbase + 4];
    const int h  = cbase >> 6;
    const int hd = cbase & 63;

    #pragma unroll
    for (int i = 0; i < 8; i++) {
        const int r    = row0 + ty * 8 + i;
        const int bidx = r >> 11;        // / Seq
        const int s    = r & 2047;
        float* dst = out + (((size_t)(bidx * Hn + h) * Seq + s) * Hd + hd);
        float4 o0 = make_float4(acc[i][0]+bb0.x, acc[i][1]+bb0.y,
                                acc[i][2]+bb0.z, acc[i][3]+bb0.w);
        float4 o1 = make_float4(acc[i][4]+bb1.x, acc[i][5]+bb1.y,
                                acc[i][6]+bb1.z, acc[i][7]+bb1.w);
        *(float4*)dst       = o0;
        *(float4*)(dst + 4) = o1;
    }
}

// ---------------------------------------------------------------------------
// Causal flash attention, fp32. BM=BN=64, HD=64, 256 threads (16x16),
// 4x4 per-thread tiles. Static smem = exactly 48KB.
// ---------------------------------------------------------------------------
__global__ __launch_bounds__(256)
void flash_kernel()
{
    const int qt = blockIdx.x;           // 0..31
    const int bh = blockIdx.y;           // 0..63

    const float* Qg = g_q + (size_t)bh * Seq * Hd;
    const float* Kg = g_k + (size_t)bh * Seq * Hd;
    const float* Vg = g_v + (size_t)bh * Seq * Hd;

    __shared__ float Qs [64][64];        // natural [i][d], pre-scaled by 1/8
    __shared__ float KPs[64][64];        // K phase: [d][j]; P phase: [i][j]
    __shared__ float Vs [64][64];        // natural [j][d]

    const int tid = threadIdx.x;
    const int tx  = tid & 15, ty = tid >> 4;

    // Load Q tile (coalesced), fold softmax scale 1/sqrt(64)=0.125
    #pragma unroll
    for (int it = 0; it < 4; it++) {
        int fid = it * 256 + tid;
        int row = fid >> 4, seg = fid & 15;
        float4 v = *(const float4*)(Qg + (size_t)(qt*64 + row) * Hd + seg * 4);
        float4 sv = make_float4(v.x*0.125f, v.y*0.125f, v.z*0.125f, v.w*0.125f);
        *(float4*)&Qs[row][seg*4] = sv;
    }

    float m_i[4], l_i[4], o[4][4];
    #pragma unroll
    for (int r = 0; r < 4; r++) {
        m_i[r] = -1e30f; l_i[r] = 0.f;
        #pragma unroll
        for (int c = 0; c < 4; c++) o[r][c] = 0.f;
    }

    for (int jt = 0; jt <= qt; jt++) {
        __syncthreads();   // previous P/V reads complete

        // Load K tile transposed into KPs[d][j]; lane-remapped so smem
        // stores are conflict-free (lanes span 32 distinct j rows).
        {
            const int row = tid & 63;          // j
            const int sb  = tid >> 6;          // 0..3
            #pragma unroll
            for (int it = 0; it < 4; it++) {
                int seg = sb + it * 4;         // 0..15
                float4 v = *(const float4*)(Kg + (size_t)(jt*64 + row) * Hd + seg * 4);
                KPs[seg*4+0][row] = v.x;
                KPs[seg*4+1][row] = v.y;
                KPs[seg*4+2][row] = v.z;
                KPs[seg*4+3][row] = v.w;
            }
        }
        // Load V tile natural (coalesced)
        #pragma unroll
        for (int it = 0; it < 4; it++) {
            int fid = it * 256 + tid;
            int row = fid >> 4, seg = fid & 15;
            *(float4*)&Vs[row][seg*4] =
                *(const float4*)(Vg + (size_t)(jt*64 + row) * Hd + seg * 4);
        }
        __syncthreads();

        // S = Qs @ KPs  (4x4 per thread), k unrolled by 4 (vector LDS)
        float s[4][4];
        #pragma unroll
        for (int r = 0; r < 4; r++)
            #pragma unroll
            for (int c = 0; c < 4; c++) s[r][c] = 0.f;

        #pragma unroll
        for (int k0 = 0; k0 < 64; k0 += 4) {
            float4 qv[4], kv[4];
            #pragma unroll
            for (int r = 0; r < 4; r++)  qv[r] = *(const float4*)&Qs[4*ty+r][k0];
            #pragma unroll
            for (int kk = 0; kk < 4; kk++) kv[kk] = *(const float4*)&KPs[k0+kk][4*tx];
            #pragma unroll
            for (int r = 0; r < 4; r++) {
                s[r][0] += qv[r].x*kv[0].x + qv[r].y*kv[1].x + qv[r].z*kv[2].x + qv[r].w*kv[3].x;
                s[r][1] += qv[r].x*kv[0].y + qv[r].y*kv[1].y + qv[r].z*kv[2].y + qv[r].w*kv[3].y;
                s[r][2] += qv[r].x*kv[0].z + qv[r].y*kv[1].z + qv[r].z*kv[2].z + qv[r].w*kv[3].z;
                s[r][3] += qv[r].x*kv[0].w + qv[r].y*kv[1].w + qv[r].z*kv[2].w + qv[r].w*kv[3].w;
            }
        }

        // Causal mask on diagonal tile
        if (jt == qt) {
            #pragma unroll
            for (int r = 0; r < 4; r++)
                #pragma unroll
                for (int c = 0; c < 4; c++)
                    if (4*tx + c > 4*ty + r) s[r][c] = -1e30f;
        }

        // Online softmax (row reductions across the 16 tx lanes)
        #pragma unroll
        for (int r = 0; r < 4; r++) {
            float mloc = fmaxf(fmaxf(s[r][0], s[r][1]), fmaxf(s[r][2], s[r][3]));
            #pragma unroll
            for (int off = 1; off < 16; off <<= 1)
                mloc = fmaxf(mloc, __shfl_xor_sync(0xffffffffu, mloc, off));
            float mnew  = fmaxf(m_i[r], mloc);
            float alpha = __expf(m_i[r] - mnew);
            float ps = 0.f;
            #pragma unroll
            for (int c = 0; c < 4; c++) {
                s[r][c] = __expf(s[r][c] - mnew);
                ps += s[r][c];
            }
            #pragma unroll
            for (int off = 1; off < 16; off <<= 1)
                ps += __shfl_xor_sync(0xffffffffu, ps, off);
            l_i[r] = l_i[r] * alpha + ps;
            m_i[r] = mnew;
            #pragma unroll
            for (int c = 0; c < 4; c++) o[r][c] *= alpha;
        }

        __syncthreads();   // all K reads done before P overwrites KPs
        #pragma unroll
        for (int r = 0; r < 4; r++)
            *(float4*)&KPs[4*ty+r][4*tx] = make_float4(s[r][0], s[r][1], s[r][2], s[r][3]);
        __syncthreads();

        // O += P @ V  (j unrolled by 4)
        #pragma unroll
        for (int j0 = 0; j0 < 64; j0 += 4) {
            float4 pv[4], vv[4];
            #pragma unroll
            for (int r = 0; r < 4; r++)  pv[r] = *(const float4*)&KPs[4*ty+r][j0];
            #pragma unroll
            for (int jj = 0; jj < 4; jj++) vv[jj] = *(const float4*)&Vs[j0+jj][4*tx];
            #pragma unroll
            for (int r = 0; r < 4; r++) {
                o[r][0] += pv[r].x*vv[0].x + pv[r].y*vv[1].x + pv[r].z*vv[2].x + pv[r].w*vv[3].x;
                o[r][1] += pv[r].x*vv[0].y + pv[r].y*vv[1].y + pv[r].z*vv[2].y + pv[r].w*vv[3].y;
                o[r][2] += pv[r].x*vv[0].z + pv[r].y*vv[1].z + pv[r].z*vv[2].z + pv[r].w*vv[3].z;
                o[r][3] += pv[r].x*vv[0].w + pv[r].y*vv[1].w + pv[r].z*vv[2].w + pv[r].w*vv[3].w;
            }
        }
    }

    // Normalize + write to [B,S,H,HD] (== [B,S,D])
    const int bidx = bh >> 4, h = bh & 15;
    #pragma unroll
    for (int r = 0; r < 4; r++) {
        float inv = 1.0f / l_i[r];
        int sg = qt * 64 + 4*ty + r;
        float* dst = g_att + (((size_t)bidx * Seq + sg) * Hn + h) * Hd + 4*tx;
        *(float4*)dst = make_float4(o[r][0]*inv, o[r][1]*inv, o[r][2]*inv, o[r][3]*inv);
    }
}

// ---------------------------------------------------------------------------
// Output projection: out = g_att @ Wo^T + bo + comp
// ---------------------------------------------------------------------------
__global__ __launch_bounds__(256)
void proj_kernel(const float* __restrict__ Wo, const float* __restrict__ bo,
                 const float* __restrict__ comp, float* __restrict__ out)
{
    float acc[8][8];
    #pragma unroll
    for (int i = 0; i < 8; i++)
        #pragma unroll
        for (int j = 0; j < 8; j++) acc[i][j] = 0.f;

    const int row0 = blockIdx.y * 128;
    const int col0 = blockIdx.x * 128;
    gemm_tile_128(g_att, Wo, Dm, row0, col0, acc);

    const int tx = threadIdx.x & 15, ty = threadIdx.x >> 4;
    const int cbase = col0 + tx * 8;
    const float4 bb0 = *(const float4*)&bo[cbase];
    const float4 bb1 = *(const float4*)&bo[cbase + 4];
    const float4 cc0 = *(const float4*)&comp[cbase];
    const float4 cc1 = *(const float4*)&comp[cbase + 4];

    #pragma unroll
    for (int i = 0; i < 8; i++) {
        const int r = row0 + ty * 8 + i;
        float* dst = out + (size_t)r * Dm + cbase;
        float4 o0 = make_float4(acc[i][0]+bb0.x+cc0.x, acc[i][1]+bb0.y+cc0.y,
                                acc[i][2]+bb0.z+cc0.z, acc[i][3]+bb0.w+cc0.w);
        float4 o1 = make_float4(acc[i][4]+bb1.x+cc1.x, acc[i][5]+bb1.y+cc1.y,
                                acc[i][6]+bb1.z+cc1.z, acc[i][7]+bb1.w+cc1.w);
        *(float4*)dst       = o0;
        *(float4*)(dst + 4) = o1;
    }
}

// ---------------------------------------------------------------------------
extern "C" void kernel_launch(void* const* d_in, const int* in_sizes, int n_in,
                              void* d_out, int out_size)
{
    (void)in_sizes; (void)n_in; (void)out_size;
    const float* X    = (const float*)d_in[0];
    const float* Wq   = (const float*)d_in[1];
    const float* bq   = (const float*)d_in[2];
    const float* Wk   = (const float*)d_in[3];
    const float* bk   = (const float*)d_in[4];
    const float* Wv   = (const float*)d_in[5];
    const float* bv   = (const float*)d_in[6];
    const float* Wo   = (const float*)d_in[7];
    const float* bo   = (const float*)d_in[8];
    const float* comp = (const float*)d_in[9];
    float* out = (float*)d_out;

    dim3 gQKV(Dm/128, Mrows/128, 3);     // (8, 64, 3)
    qkv_kernel<<<gQKV, 256>>>(X, Wq, bq, Wk, bk, Wv, bv);

    dim3 gFA(Seq/64, Bsz*Hn);            // (32, 64)
    flash_kernel<<<gFA, 256>>>();

    dim3 gP(Dm/128, Mrows/128);          // (8, 64)
    proj_kernel<<<gP, 256>>>(Wo, bo, comp, out);
}

// round 4
// speedup vs baseline: 1.1380x; 1.1380x over previous
#include <cuda_runtime.h>
#include <cstdint>

#define Bsz 4
#define Seq 2048
#define Dm  1024
#define Hn  16
#define Hd  64
#define Mrows (Bsz*Seq)   // 8192

// Scratch (allocation-free rule: __device__ globals)
__device__ float g_q[Bsz*Hn*Seq*Hd];     // [B,H,S,HD]
__device__ float g_k[Bsz*Hn*Seq*Hd];
__device__ float g_v[Bsz*Hn*Seq*Hd];
__device__ float g_att[Bsz*Seq*Dm];      // [B,S,D] (D = h*64+hd)

// ===========================================================================
// 3xTF32 mma.sync GEMM:  C[128x128] tile of X[M,K] @ W[N,K]^T, K=1024
// 8 warps = 2(M) x 4(N); per warp 64x32; m16n8k8 fragments.
// Each operand split hi/lo (tf32) -> 3 MMAs per pair: fp32-quality result.
// ===========================================================================
#define KT   32
#define PAD  36                      // floats per smem row (bank-conflict-free)
#define STAGE_F (128*PAD)            // floats per operand stage
#define GEMM_SMEM_BYTES (4*STAGE_F*4)  // A0,B0,A1,B1 = 73728 B

__device__ __forceinline__ uint32_t smem_u32(const void* p) {
    uint32_t a;
    asm("{ .reg .u64 t; cvta.to.shared.u64 t, %1; cvt.u32.u64 %0, t; }"
        : "=r"(a) : "l"(p));
    return a;
}

#define CP16(dst, src) \
    asm volatile("cp.async.cg.shared.global [%0], [%1], 16;" :: "r"(dst), "l"(src))
#define CP_COMMIT()  asm volatile("cp.async.commit_group;" ::: "memory")
#define CP_WAIT1()   asm volatile("cp.async.wait_group 1;" ::: "memory")
#define CP_WAIT0()   asm volatile("cp.async.wait_group 0;" ::: "memory")

__device__ __forceinline__ uint32_t f2tf32(float x) {
    uint32_t r;
    asm("cvt.rna.tf32.f32 %0, %1;" : "=r"(r) : "f"(x));
    return r;
}

__device__ __forceinline__ void mma_tf32_16x8x8(float c[4], const uint32_t a[4],
                                                const uint32_t b[2]) {
    asm volatile(
        "mma.sync.aligned.m16n8k8.row.col.f32.tf32.tf32.f32 "
        "{%0,%1,%2,%3}, {%4,%5,%6,%7}, {%8,%9}, {%0,%1,%2,%3};"
        : "+f"(c[0]), "+f"(c[1]), "+f"(c[2]), "+f"(c[3])
        : "r"(a[0]), "r"(a[1]), "r"(a[2]), "r"(a[3]), "r"(b[0]), "r"(b[1]));
}

// Fills acc[mi][ni][4] for this thread's fragments.
__device__ __forceinline__ void gemm_mma_tile(const float* __restrict__ X,
                                              const float* __restrict__ W,
                                              int row0, int col0,
                                              float acc[4][4][4])
{
    extern __shared__ float sm[];
    const int tid  = threadIdx.x;
    const int wid  = tid >> 5, lane = tid & 31;
    const int warpM = wid >> 2, warpN = wid & 3;
    const int quad = lane >> 2, tq = lane & 3;

    // cp.async slots: 1024 16B-chunks per operand stage, 4 per thread
    uint32_t dA[4], dB[4];
    const float* sA[4];
    const float* sB[4];
    const uint32_t smb = smem_u32(sm);
    #pragma unroll
    for (int it = 0; it < 4; it++) {
        int id = it * 256 + tid;         // 0..1023
        int r  = id >> 3;                // row 0..127
        int c  = id & 7;                 // 16B chunk
        dA[it] = smb + (uint32_t)(r * PAD + c * 4) * 4u;
        dB[it] = dA[it] + STAGE_F * 4u;
        sA[it] = X + (size_t)(row0 + r) * Dm + c * 4;
        sB[it] = W + (size_t)(col0 + r) * Dm + c * 4;
    }
    const uint32_t stageOff = 2u * STAGE_F * 4u;   // bytes between stages

    const float* As = sm;
    const float* Bs = sm + STAGE_F;
    const int aRow0 = warpM * 64 + quad;           // + mi*16 (+8)
    const int bRow0 = warpN * 32 + quad;           // + ni*8

    // Prologue: stage 0
    #pragma unroll
    for (int it = 0; it < 4; it++) { CP16(dA[it], sA[it]); CP16(dB[it], sB[it]); }
    CP_COMMIT();

    const int NST = Dm / KT;                        // 32 stages
    for (int s = 0; s < NST; s++) {
        const int cur = s & 1;
        if (s + 1 < NST) {
            const uint32_t bo = (uint32_t)((s + 1) & 1) * stageOff;
            const int ko = (s + 1) * KT;
            #pragma unroll
            for (int it = 0; it < 4; it++) {
                CP16(dA[it] + bo, sA[it] + ko);
                CP16(dB[it] + bo, sB[it] + ko);
            }
            CP_COMMIT();
            CP_WAIT1();
        } else {
            CP_WAIT0();
        }
        __syncthreads();

        const float* Ab = As + cur * 2 * STAGE_F;
        const float* Bb = Bs + cur * 2 * STAGE_F;

        #pragma unroll
        for (int kk = 0; kk < 4; kk++) {
            const int k0 = kk * 8 + tq;
            uint32_t ah[4][4], al[4][4], bh[4][2], bl[4][2];
            #pragma unroll
            for (int mi = 0; mi < 4; mi++) {
                const float* p = Ab + (aRow0 + mi * 16) * PAD + k0;
                float v0 = p[0], v1 = p[8 * PAD], v2 = p[4], v3 = p[8 * PAD + 4];
                ah[mi][0] = f2tf32(v0); al[mi][0] = f2tf32(v0 - __uint_as_float(ah[mi][0]));
                ah[mi][1] = f2tf32(v1); al[mi][1] = f2tf32(v1 - __uint_as_float(ah[mi][1]));
                ah[mi][2] = f2tf32(v2); al[mi][2] = f2tf32(v2 - __uint_as_float(ah[mi][2]));
                ah[mi][3] = f2tf32(v3); al[mi][3] = f2tf32(v3 - __uint_as_float(ah[mi][3]));
            }
            #pragma unroll
            for (int ni = 0; ni < 4; ni++) {
                const float* p = Bb + (bRow0 + ni * 8) * PAD + k0;
                float v0 = p[0], v1 = p[4];
                bh[ni][0] = f2tf32(v0); bl[ni][0] = f2tf32(v0 - __uint_as_float(bh[ni][0]));
                bh[ni][1] = f2tf32(v1); bl[ni][1] = f2tf32(v1 - __uint_as_float(bh[ni][1]));
            }
            #pragma unroll
            for (int mi = 0; mi < 4; mi++)
                #pragma unroll
                for (int ni = 0; ni < 4; ni++) {
                    mma_tf32_16x8x8(acc[mi][ni], al[mi], bh[ni]);
                    mma_tf32_16x8x8(acc[mi][ni], ah[mi], bl[ni]);
                    mma_tf32_16x8x8(acc[mi][ni], ah[mi], bh[ni]);
                }
        }
        __syncthreads();
    }
}

// ===========================================================================
// QKV projection: grid.z selects {Q,K,V}; scatter to [B,H,S,HD]
// ===========================================================================
__global__ __launch_bounds__(256)
void qkv_mma(const float* __restrict__ X,
             const float* __restrict__ Wq, const float* __restrict__ bq,
             const float* __restrict__ Wk, const float* __restrict__ bk,
             const float* __restrict__ Wv, const float* __restrict__ bv)
{
    const float *W, *bias;
    float* out;
    if (blockIdx.z == 0)      { W = Wq; bias = bq; out = g_q; }
    else if (blockIdx.z == 1) { W = Wk; bias = bk; out = g_k; }
    else                      { W = Wv; bias = bv; out = g_v; }

    float acc[4][4][4];
    #pragma unroll
    for (int mi = 0; mi < 4; mi++)
        #pragma unroll
        for (int ni = 0; ni < 4; ni++)
            #pragma unroll
            for (int j = 0; j < 4; j++) acc[mi][ni][j] = 0.f;

    const int row0 = blockIdx.y * 128;
    const int col0 = blockIdx.x * 128;
    gemm_mma_tile(X, W, row0, col0, acc);

    const int tid  = threadIdx.x;
    const int wid  = tid >> 5, lane = tid & 31;
    const int warpM = wid >> 2, warpN = wid & 3;
    const int quad = lane >> 2, tq = lane & 3;

    #pragma unroll
    for (int mi = 0; mi < 4; mi++) {
        #pragma unroll
        for (int half = 0; half < 2; half++) {
            const int r = row0 + warpM * 64 + mi * 16 + quad + half * 8;
            const int b = r >> 11;
            const int sq = r & 2047;
            #pragma unroll
            for (int ni = 0; ni < 4; ni++) {
                const int c  = col0 + warpN * 32 + ni * 8 + 2 * tq;
                const int h  = c >> 6;
                const int hd = c & 63;
                float2 bb = *(const float2*)&bias[c];
                float2 v;
                v.x = acc[mi][ni][half * 2 + 0] + bb.x;
                v.y = acc[mi][ni][half * 2 + 1] + bb.y;
                *(float2*)(out + (((size_t)(b * Hn + h) * Seq + sq) * Hd + hd)) = v;
            }
        }
    }
}

// ===========================================================================
// Output projection: out = g_att @ Wo^T + bo + comp
// ===========================================================================
__global__ __launch_bounds__(256)
void proj_mma(const float* __restrict__ Wo, const float* __restrict__ bo,
              const float* __restrict__ comp, float* __restrict__ out)
{
    float acc[4][4][4];
    #pragma unroll
    for (int mi = 0; mi < 4; mi++)
        #pragma unroll
        for (int ni = 0; ni < 4; ni++)
            #pragma unroll
            for (int j = 0; j < 4; j++) acc[mi][ni][j] = 0.f;

    const int row0 = blockIdx.y * 128;
    const int col0 = blockIdx.x * 128;
    gemm_mma_tile(g_att, Wo, row0, col0, acc);

    const int tid  = threadIdx.x;
    const int wid  = tid >> 5, lane = tid & 31;
    const int warpM = wid >> 2, warpN = wid & 3;
    const int quad = lane >> 2, tq = lane & 3;

    #pragma unroll
    for (int mi = 0; mi < 4; mi++) {
        #pragma unroll
        for (int half = 0; half < 2; half++) {
            const int r = row0 + warpM * 64 + mi * 16 + quad + half * 8;
            #pragma unroll
            for (int ni = 0; ni < 4; ni++) {
                const int c = col0 + warpN * 32 + ni * 8 + 2 * tq;
                float2 bb = *(const float2*)&bo[c];
                float2 cc = *(const float2*)&comp[c];
                float2 v;
                v.x = acc[mi][ni][half * 2 + 0] + bb.x + cc.x;
                v.y = acc[mi][ni][half * 2 + 1] + bb.y + cc.y;
                *(float2*)(out + (size_t)r * Dm + c) = v;
            }
        }
    }
}

// ===========================================================================
// Causal flash attention, fp32 SIMT (known-good). BM=BN=64, HD=64.
// ===========================================================================
__global__ __launch_bounds__(256)
void flash_kernel()
{
    const int qt = blockIdx.x;
    const int bh = blockIdx.y;

    const float* Qg = g_q + (size_t)bh * Seq * Hd;
    const float* Kg = g_k + (size_t)bh * Seq * Hd;
    const float* Vg = g_v + (size_t)bh * Seq * Hd;

    __shared__ float Qs [64][64];
    __shared__ float KPs[64][64];
    __shared__ float Vs [64][64];

    const int tid = threadIdx.x;
    const int tx  = tid & 15, ty = tid >> 4;

    #pragma unroll
    for (int it = 0; it < 4; it++) {
        int fid = it * 256 + tid;
        int row = fid >> 4, seg = fid & 15;
        float4 v = *(const float4*)(Qg + (size_t)(qt*64 + row) * Hd + seg * 4);
        float4 sv = make_float4(v.x*0.125f, v.y*0.125f, v.z*0.125f, v.w*0.125f);
        *(float4*)&Qs[row][seg*4] = sv;
    }

    float m_i[4], l_i[4], o[4][4];
    #pragma unroll
    for (int r = 0; r < 4; r++) {
        m_i[r] = -1e30f; l_i[r] = 0.f;
        #pragma unroll
        for (int c = 0; c < 4; c++) o[r][c] = 0.f;
    }

    for (int jt = 0; jt <= qt; jt++) {
        __syncthreads();

        {
            const int row = tid & 63;
            const int sb  = tid >> 6;
            #pragma unroll
            for (int it = 0; it < 4; it++) {
                int seg = sb + it * 4;
                float4 v = *(const float4*)(Kg + (size_t)(jt*64 + row) * Hd + seg * 4);
                KPs[seg*4+0][row] = v.x;
                KPs[seg*4+1][row] = v.y;
                KPs[seg*4+2][row] = v.z;
                KPs[seg*4+3][row] = v.w;
            }
        }
        #pragma unroll
        for (int it = 0; it < 4; it++) {
            int fid = it * 256 + tid;
            int row = fid >> 4, seg = fid & 15;
            *(float4*)&Vs[row][seg*4] =
                *(const float4*)(Vg + (size_t)(jt*64 + row) * Hd + seg * 4);
        }
        __syncthreads();

        float s[4][4];
        #pragma unroll
        for (int r = 0; r < 4; r++)
            #pragma unroll
            for (int c = 0; c < 4; c++) s[r][c] = 0.f;

        #pragma unroll
        for (int k0 = 0; k0 < 64; k0 += 4) {
            float4 qv[4], kv[4];
            #pragma unroll
            for (int r = 0; r < 4; r++)  qv[r] = *(const float4*)&Qs[4*ty+r][k0];
            #pragma unroll
            for (int kk = 0; kk < 4; kk++) kv[kk] = *(const float4*)&KPs[k0+kk][4*tx];
            #pragma unroll
            for (int r = 0; r < 4; r++) {
                s[r][0] += qv[r].x*kv[0].x + qv[r].y*kv[1].x + qv[r].z*kv[2].x + qv[r].w*kv[3].x;
                s[r][1] += qv[r].x*kv[0].y + qv[r].y*kv[1].y + qv[r].z*kv[2].y + qv[r].w*kv[3].y;
                s[r][2] += qv[r].x*kv[0].z + qv[r].y*kv[1].z + qv[r].z*kv[2].z + qv[r].w*kv[3].z;
                s[r][3] += qv[r].x*kv[0].w + qv[r].y*kv[1].w + qv[r].z*kv[2].w + qv[r].w*kv[3].w;
            }
        }

        if (jt == qt) {
            #pragma unroll
            for (int r = 0; r < 4; r++)
                #pragma unroll
                for (int c = 0; c < 4; c++)
                    if (4*tx + c > 4*ty + r) s[r][c] = -1e30f;
        }

        #pragma unroll
        for (int r = 0; r < 4; r++) {
            float mloc = fmaxf(fmaxf(s[r][0], s[r][1]), fmaxf(s[r][2], s[r][3]));
            #pragma unroll
            for (int off = 1; off < 16; off <<= 1)
                mloc = fmaxf(mloc, __shfl_xor_sync(0xffffffffu, mloc, off));
            float mnew  = fmaxf(m_i[r], mloc);
            float alpha = __expf(m_i[r] - mnew);
            float ps = 0.f;
            #pragma unroll
            for (int c = 0; c < 4; c++) {
                s[r][c] = __expf(s[r][c] - mnew);
                ps += s[r][c];
            }
            #pragma unroll
            for (int off = 1; off < 16; off <<= 1)
                ps += __shfl_xor_sync(0xffffffffu, ps, off);
            l_i[r] = l_i[r] * alpha + ps;
            m_i[r] = mnew;
            #pragma unroll
            for (int c = 0; c < 4; c++) o[r][c] *= alpha;
        }

        __syncthreads();
        #pragma unroll
        for (int r = 0; r < 4; r++)
            *(float4*)&KPs[4*ty+r][4*tx] = make_float4(s[r][0], s[r][1], s[r][2], s[r][3]);
        __syncthreads();

        #pragma unroll
        for (int j0 = 0; j0 < 64; j0 += 4) {
            float4 pv[4], vv[4];
            #pragma unroll
            for (int r = 0; r < 4; r++)  pv[r] = *(const float4*)&KPs[4*ty+r][j0];
            #pragma unroll
            for (int jj = 0; jj < 4; jj++) vv[jj] = *(const float4*)&Vs[j0+jj][4*tx];
            #pragma unroll
            for (int r = 0; r < 4; r++) {
                o[r][0] += pv[r].x*vv[0].x + pv[r].y*vv[1].x + pv[r].z*vv[2].x + pv[r].w*vv[3].x;
                o[r][1] += pv[r].x*vv[0].y + pv[r].y*vv[1].y + pv[r].z*vv[2].y + pv[r].w*vv[3].y;
                o[r][2] += pv[r].x*vv[0].z + pv[r].y*vv[1].z + pv[r].z*vv[2].z + pv[r].w*vv[3].z;
                o[r][3] += pv[r].x*vv[0].w + pv[r].y*vv[1].w + pv[r].z*vv[2].w + pv[r].w*vv[3].w;
            }
        }
    }

    const int bidx = bh >> 4, h = bh & 15;
    #pragma unroll
    for (int r = 0; r < 4; r++) {
        float inv = 1.0f / l_i[r];
        int sg = qt * 64 + 4*ty + r;
        float* dst = g_att + (((size_t)bidx * Seq + sg) * Hn + h) * Hd + 4*tx;
        *(float4*)dst = make_float4(o[r][0]*inv, o[r][1]*inv, o[r][2]*inv, o[r][3]*inv);
    }
}

// ---------------------------------------------------------------------------
extern "C" void kernel_launch(void* const* d_in, const int* in_sizes, int n_in,
                              void* d_out, int out_size)
{
    (void)in_sizes; (void)n_in; (void)out_size;
    const float* X    = (const float*)d_in[0];
    const float* Wq   = (const float*)d_in[1];
    const float* bq   = (const float*)d_in[2];
    const float* Wk   = (const float*)d_in[3];
    const float* bk   = (const float*)d_in[4];
    const float* Wv   = (const float*)d_in[5];
    const float* bv   = (const float*)d_in[6];
    const float* Wo   = (const float*)d_in[7];
    const float* bo   = (const float*)d_in[8];
    const float* comp = (const float*)d_in[9];
    float* out = (float*)d_out;

    cudaFuncSetAttribute(qkv_mma,  cudaFuncAttributeMaxDynamicSharedMemorySize, GEMM_SMEM_BYTES);
    cudaFuncSetAttribute(proj_mma, cudaFuncAttributeMaxDynamicSharedMemorySize, GEMM_SMEM_BYTES);

    dim3 gQKV(Dm/128, Mrows/128, 3);     // (8, 64, 3)
    qkv_mma<<<gQKV, 256, GEMM_SMEM_BYTES>>>(X, Wq, bq, Wk, bk, Wv, bv);

    dim3 gFA(Seq/64, Bsz*Hn);            // (32, 64)
    flash_kernel<<<gFA, 256>>>();

    dim3 gP(Dm/128, Mrows/128);          // (8, 64)
    proj_mma<<<gP, 256, GEMM_SMEM_BYTES>>>(Wo, bo, comp, out);
}

// round 5
// speedup vs baseline: 1.2494x; 1.0978x over previous
#include <cuda_runtime.h>
#include <cstdint>

#define Bsz 4
#define Seq 2048
#define Dm  1024
#define Hn  16
#define Hd  64
#define Mrows (Bsz*Seq)   // 8192

// Scratch (allocation-free rule: __device__ globals)
__device__ float g_q[Bsz*Hn*Seq*Hd];     // [B,H,S,HD]
__device__ float g_k[Bsz*Hn*Seq*Hd];
__device__ float g_v[Bsz*Hn*Seq*Hd];
__device__ float g_att[Bsz*Seq*Dm];      // [B,S,D] (D = h*64+hd)

// ===========================================================================
// Common PTX helpers
// ===========================================================================
__device__ __forceinline__ uint32_t smem_u32(const void* p) {
    uint32_t a;
    asm("{ .reg .u64 t; cvta.to.shared.u64 t, %1; cvt.u32.u64 %0, t; }"
        : "=r"(a) : "l"(p));
    return a;
}

#define CP16(dst, src) \
    asm volatile("cp.async.cg.shared.global [%0], [%1], 16;" :: "r"(dst), "l"(src))
#define CP_COMMIT()  asm volatile("cp.async.commit_group;" ::: "memory")
#define CP_WAIT1()   asm volatile("cp.async.wait_group 1;" ::: "memory")
#define CP_WAIT0()   asm volatile("cp.async.wait_group 0;" ::: "memory")

__device__ __forceinline__ uint32_t f2tf32(float x) {
    uint32_t r;
    asm("cvt.rna.tf32.f32 %0, %1;" : "=r"(r) : "f"(x));
    return r;
}

__device__ __forceinline__ void mma_tf32_16x8x8(float c[4], const uint32_t a[4],
                                                uint32_t b0, uint32_t b1) {
    asm volatile(
        "mma.sync.aligned.m16n8k8.row.col.f32.tf32.tf32.f32 "
        "{%0,%1,%2,%3}, {%4,%5,%6,%7}, {%8,%9}, {%0,%1,%2,%3};"
        : "+f"(c[0]), "+f"(c[1]), "+f"(c[2]), "+f"(c[3])
        : "r"(a[0]), "r"(a[1]), "r"(a[2]), "r"(a[3]), "r"(b0), "r"(b1));
}

// ===========================================================================
// 3xTF32 mma.sync GEMM (proven R4):  C[128x128] tile of X @ W^T, K=1024
// ===========================================================================
#define KT   32
#define PAD  36
#define STAGE_F (128*PAD)
#define GEMM_SMEM_BYTES (4*STAGE_F*4)

__device__ __forceinline__ void gemm_mma_tile(const float* __restrict__ X,
                                              const float* __restrict__ W,
                                              int row0, int col0,
                                              float acc[4][4][4])
{
    extern __shared__ float sm[];
    const int tid  = threadIdx.x;
    const int wid  = tid >> 5, lane = tid & 31;
    const int warpM = wid >> 2, warpN = wid & 3;
    const int quad = lane >> 2, tq = lane & 3;

    uint32_t dA[4], dB[4];
    const float* sA[4];
    const float* sB[4];
    const uint32_t smb = smem_u32(sm);
    #pragma unroll
    for (int it = 0; it < 4; it++) {
        int id = it * 256 + tid;
        int r  = id >> 3;
        int c  = id & 7;
        dA[it] = smb + (uint32_t)(r * PAD + c * 4) * 4u;
        dB[it] = dA[it] + STAGE_F * 4u;
        sA[it] = X + (size_t)(row0 + r) * Dm + c * 4;
        sB[it] = W + (size_t)(col0 + r) * Dm + c * 4;
    }
    const uint32_t stageOff = 2u * STAGE_F * 4u;

    const float* As = sm;
    const float* Bs = sm + STAGE_F;
    const int aRow0 = warpM * 64 + quad;
    const int bRow0 = warpN * 32 + quad;

    #pragma unroll
    for (int it = 0; it < 4; it++) { CP16(dA[it], sA[it]); CP16(dB[it], sB[it]); }
    CP_COMMIT();

    const int NST = Dm / KT;
    for (int s = 0; s < NST; s++) {
        const int cur = s & 1;
        if (s + 1 < NST) {
            const uint32_t bo = (uint32_t)((s + 1) & 1) * stageOff;
            const int ko = (s + 1) * KT;
            #pragma unroll
            for (int it = 0; it < 4; it++) {
                CP16(dA[it] + bo, sA[it] + ko);
                CP16(dB[it] + bo, sB[it] + ko);
            }
            CP_COMMIT();
            CP_WAIT1();
        } else {
            CP_WAIT0();
        }
        __syncthreads();

        const float* Ab = As + cur * 2 * STAGE_F;
        const float* Bb = Bs + cur * 2 * STAGE_F;

        #pragma unroll
        for (int kk = 0; kk < 4; kk++) {
            const int k0 = kk * 8 + tq;
            uint32_t ah[4][4], al[4][4], bh[4][2], bl[4][2];
            #pragma unroll
            for (int mi = 0; mi < 4; mi++) {
                const float* p = Ab + (aRow0 + mi * 16) * PAD + k0;
                float v0 = p[0], v1 = p[8 * PAD], v2 = p[4], v3 = p[8 * PAD + 4];
                ah[mi][0] = f2tf32(v0); al[mi][0] = f2tf32(v0 - __uint_as_float(ah[mi][0]));
                ah[mi][1] = f2tf32(v1); al[mi][1] = f2tf32(v1 - __uint_as_float(ah[mi][1]));
                ah[mi][2] = f2tf32(v2); al[mi][2] = f2tf32(v2 - __uint_as_float(ah[mi][2]));
                ah[mi][3] = f2tf32(v3); al[mi][3] = f2tf32(v3 - __uint_as_float(ah[mi][3]));
            }
            #pragma unroll
            for (int ni = 0; ni < 4; ni++) {
                const float* p = Bb + (bRow0 + ni * 8) * PAD + k0;
                float v0 = p[0], v1 = p[4];
                bh[ni][0] = f2tf32(v0); bl[ni][0] = f2tf32(v0 - __uint_as_float(bh[ni][0]));
                bh[ni][1] = f2tf32(v1); bl[ni][1] = f2tf32(v1 - __uint_as_float(bh[ni][1]));
            }
            #pragma unroll
            for (int mi = 0; mi < 4; mi++)
                #pragma unroll
                for (int ni = 0; ni < 4; ni++) {
                    mma_tf32_16x8x8(acc[mi][ni], al[mi], bh[ni][0], bh[ni][1]);
                    mma_tf32_16x8x8(acc[mi][ni], ah[mi], bl[ni][0], bl[ni][1]);
                    mma_tf32_16x8x8(acc[mi][ni], ah[mi], bh[ni][0], bh[ni][1]);
                }
        }
        __syncthreads();
    }
}

__global__ __launch_bounds__(256)
void qkv_mma(const float* __restrict__ X,
             const float* __restrict__ Wq, const float* __restrict__ bq,
             const float* __restrict__ Wk, const float* __restrict__ bk,
             const float* __restrict__ Wv, const float* __restrict__ bv)
{
    const float *W, *bias;
    float* out;
    if (blockIdx.z == 0)      { W = Wq; bias = bq; out = g_q; }
    else if (blockIdx.z == 1) { W = Wk; bias = bk; out = g_k; }
    else                      { W = Wv; bias = bv; out = g_v; }

    float acc[4][4][4];
    #pragma unroll
    for (int mi = 0; mi < 4; mi++)
        #pragma unroll
        for (int ni = 0; ni < 4; ni++)
            #pragma unroll
            for (int j = 0; j < 4; j++) acc[mi][ni][j] = 0.f;

    const int row0 = blockIdx.y * 128;
    const int col0 = blockIdx.x * 128;
    gemm_mma_tile(X, W, row0, col0, acc);

    const int tid  = threadIdx.x;
    const int wid  = tid >> 5, lane = tid & 31;
    const int warpM = wid >> 2, warpN = wid & 3;
    const int quad = lane >> 2, tq = lane & 3;

    #pragma unroll
    for (int mi = 0; mi < 4; mi++) {
        #pragma unroll
        for (int half = 0; half < 2; half++) {
            const int r = row0 + warpM * 64 + mi * 16 + quad + half * 8;
            const int b = r >> 11;
            const int sq = r & 2047;
            #pragma unroll
            for (int ni = 0; ni < 4; ni++) {
                const int c  = col0 + warpN * 32 + ni * 8 + 2 * tq;
                const int h  = c >> 6;
                const int hd = c & 63;
                float2 bb = *(const float2*)&bias[c];
                float2 v;
                v.x = acc[mi][ni][half * 2 + 0] + bb.x;
                v.y = acc[mi][ni][half * 2 + 1] + bb.y;
                *(float2*)(out + (((size_t)(b * Hn + h) * Seq + sq) * Hd + hd)) = v;
            }
        }
    }
}

__global__ __launch_bounds__(256)
void proj_mma(const float* __restrict__ Wo, const float* __restrict__ bo,
              const float* __restrict__ comp, float* __restrict__ out)
{
    float acc[4][4][4];
    #pragma unroll
    for (int mi = 0; mi < 4; mi++)
        #pragma unroll
        for (int ni = 0; ni < 4; ni++)
            #pragma unroll
            for (int j = 0; j < 4; j++) acc[mi][ni][j] = 0.f;

    const int row0 = blockIdx.y * 128;
    const int col0 = blockIdx.x * 128;
    gemm_mma_tile(g_att, Wo, row0, col0, acc);

    const int tid  = threadIdx.x;
    const int wid  = tid >> 5, lane = tid & 31;
    const int warpM = wid >> 2, warpN = wid & 3;
    const int quad = lane >> 2, tq = lane & 3;

    #pragma unroll
    for (int mi = 0; mi < 4; mi++) {
        #pragma unroll
        for (int half = 0; half < 2; half++) {
            const int r = row0 + warpM * 64 + mi * 16 + quad + half * 8;
            #pragma unroll
            for (int ni = 0; ni < 4; ni++) {
                const int c = col0 + warpN * 32 + ni * 8 + 2 * tq;
                float2 bb = *(const float2*)&bo[c];
                float2 cc = *(const float2*)&comp[c];
                float2 v;
                v.x = acc[mi][ni][half * 2 + 0] + bb.x + cc.x;
                v.y = acc[mi][ni][half * 2 + 1] + bb.y + cc.y;
                *(float2*)(out + (size_t)r * Dm + c) = v;
            }
        }
    }
}

// ===========================================================================
// Flash attention with 3xTF32 mma. BM=BN=64, 4 warps (128 thr), warp=16 rows.
// K/V tiles double-buffered cp.async. V read transposed via PAD=72 layout.
// ===========================================================================
#define PQ   68                    // pad for Q/K/P tiles (4*quad+tq banks)
#define PVV  72                    // pad for V tile (8*tq+quad banks)
#define QS_F   (64*PQ)             // 4352 floats
#define VS_F   (64*PVV)            // 4608 floats
#define FLASH_SMEM_BYTES ((QS_F*3 + VS_F*2)*4)   // Qs/Ps + Ks*2 + Vs*2 = 89088

__global__ __launch_bounds__(128)
void flash_mma()
{
    const int qt = blockIdx.x;           // 0..31
    const int bh = blockIdx.y;           // 0..63

    const float* Qg = g_q + (size_t)bh * Seq * Hd;
    const float* Kg = g_k + (size_t)bh * Seq * Hd;
    const float* Vg = g_v + (size_t)bh * Seq * Hd;

    extern __shared__ float fs[];
    float* Qs  = fs;                       // also Ps after Q-frag extraction
    float* Ksb[2] = { fs + QS_F, fs + 2*QS_F };
    float* Vsb[2] = { fs + 3*QS_F, fs + 3*QS_F + VS_F };

    const int tid  = threadIdx.x;
    const int wid  = tid >> 5, lane = tid & 31;
    const int quad = lane >> 2, tq = lane & 3;
    const int r0   = wid * 16;

    // Per-thread cp.async slots: 8 x 16B chunks per 64x64 tile
    int crow[8], cseg[8];
    #pragma unroll
    for (int i = 0; i < 8; i++) {
        int id = i * 128 + tid;
        crow[i] = id >> 4;
        cseg[i] = id & 15;
    }
    const uint32_t qsb = smem_u32(Qs);
    const uint32_t ks0 = smem_u32(Ksb[0]), ks1 = smem_u32(Ksb[1]);
    const uint32_t vs0 = smem_u32(Vsb[0]), vs1 = smem_u32(Vsb[1]);

    // Prologue: Q tile + K/V tile 0 (one group)
    #pragma unroll
    for (int i = 0; i < 8; i++) {
        CP16(qsb + (uint32_t)(crow[i]*PQ + cseg[i]*4)*4u,
             Qg + (size_t)(qt*64 + crow[i]) * Hd + cseg[i]*4);
        CP16(ks0 + (uint32_t)(crow[i]*PQ + cseg[i]*4)*4u,
             Kg + (size_t)(crow[i]) * Hd + cseg[i]*4);
        CP16(vs0 + (uint32_t)(crow[i]*PVV + cseg[i]*4)*4u,
             Vg + (size_t)(crow[i]) * Hd + cseg[i]*4);
    }
    CP_COMMIT();
    CP_WAIT0();
    __syncthreads();

    // Extract Q A-frags (scaled by 1/8), split hi/lo. Qs freed -> Ps.
    uint32_t qhi[8][4], qlo[8][4];
    #pragma unroll
    for (int kk = 0; kk < 8; kk++) {
        const int k0 = kk * 8 + tq;
        float v0 = Qs[(r0 + quad)     * PQ + k0]     * 0.125f;
        float v1 = Qs[(r0 + quad + 8) * PQ + k0]     * 0.125f;
        float v2 = Qs[(r0 + quad)     * PQ + k0 + 4] * 0.125f;
        float v3 = Qs[(r0 + quad + 8) * PQ + k0 + 4] * 0.125f;
        qhi[kk][0] = f2tf32(v0); qlo[kk][0] = f2tf32(v0 - __uint_as_float(qhi[kk][0]));
        qhi[kk][1] = f2tf32(v1); qlo[kk][1] = f2tf32(v1 - __uint_as_float(qhi[kk][1]));
        qhi[kk][2] = f2tf32(v2); qlo[kk][2] = f2tf32(v2 - __uint_as_float(qhi[kk][2]));
        qhi[kk][3] = f2tf32(v3); qlo[kk][3] = f2tf32(v3 - __uint_as_float(qhi[kk][3]));
    }
    float* Ps = Qs;

    float m_i[2] = { -1e30f, -1e30f };
    float l_i[2] = { 0.f, 0.f };
    float oacc[8][4];
    #pragma unroll
    for (int ni = 0; ni < 8; ni++)
        #pragma unroll
        for (int j = 0; j < 4; j++) oacc[ni][j] = 0.f;

    for (int jt = 0; jt <= qt; jt++) {
        __syncthreads();   // all reads of buffer (jt+1)&1 from iter jt-1 done

        const int cur = jt & 1;
        if (jt + 1 <= qt) {
            const uint32_t kd = (jt + 1) & 1 ? ks1 : ks0;
            const uint32_t vd = (jt + 1) & 1 ? vs1 : vs0;
            const size_t roff = (size_t)((jt + 1) * 64);
            #pragma unroll
            for (int i = 0; i < 8; i++) {
                CP16(kd + (uint32_t)(crow[i]*PQ + cseg[i]*4)*4u,
                     Kg + (roff + crow[i]) * Hd + cseg[i]*4);
                CP16(vd + (uint32_t)(crow[i]*PVV + cseg[i]*4)*4u,
                     Vg + (roff + crow[i]) * Hd + cseg[i]*4);
            }
            CP_COMMIT();
            CP_WAIT1();
        } else {
            CP_WAIT0();
        }
        __syncthreads();

        const float* Ks = Ksb[cur];
        const float* Vs = Vsb[cur];

        // ---- S = Q K^T (3xTF32) ----
        float sacc[8][4];
        #pragma unroll
        for (int ni = 0; ni < 8; ni++)
            #pragma unroll
            for (int j = 0; j < 4; j++) sacc[ni][j] = 0.f;

        #pragma unroll
        for (int ni = 0; ni < 8; ni++) {
            const float* kb = Ks + (ni * 8 + quad) * PQ;
            #pragma unroll
            for (int kk = 0; kk < 8; kk++) {
                const int k0 = kk * 8 + tq;
                float v0 = kb[k0], v1 = kb[k0 + 4];
                uint32_t bh0 = f2tf32(v0), bl0 = f2tf32(v0 - __uint_as_float(bh0));
                uint32_t bh1 = f2tf32(v1), bl1 = f2tf32(v1 - __uint_as_float(bh1));
                mma_tf32_16x8x8(sacc[ni], qlo[kk], bh0, bh1);
                mma_tf32_16x8x8(sacc[ni], qhi[kk], bl0, bl1);
                mma_tf32_16x8x8(sacc[ni], qhi[kk], bh0, bh1);
            }
        }

        // ---- causal mask on diagonal tile ----
        if (jt == qt) {
            const int ib0 = r0 + quad;        // within-tile row (half 0)
            #pragma unroll
            for (int ni = 0; ni < 8; ni++) {
                const int jb = ni * 8 + 2 * tq;
                if (jb     > ib0)     sacc[ni][0] = -1e30f;
                if (jb + 1 > ib0)     sacc[ni][1] = -1e30f;
                if (jb     > ib0 + 8) sacc[ni][2] = -1e30f;
                if (jb + 1 > ib0 + 8) sacc[ni][3] = -1e30f;
            }
        }

        // ---- online softmax (rows quad, quad+8; 4-lane reductions) ----
        float mloc0 = -1e30f, mloc1 = -1e30f;
        #pragma unroll
        for (int ni = 0; ni < 8; ni++) {
            mloc0 = fmaxf(mloc0, fmaxf(sacc[ni][0], sacc[ni][1]));
            mloc1 = fmaxf(mloc1, fmaxf(sacc[ni][2], sacc[ni][3]));
        }
        #pragma unroll
        for (int off = 1; off < 4; off <<= 1) {
            mloc0 = fmaxf(mloc0, __shfl_xor_sync(0xffffffffu, mloc0, off));
            mloc1 = fmaxf(mloc1, __shfl_xor_sync(0xffffffffu, mloc1, off));
        }
        const float mnew0 = fmaxf(m_i[0], mloc0);
        const float mnew1 = fmaxf(m_i[1], mloc1);
        const float al0 = __expf(m_i[0] - mnew0);
        const float al1 = __expf(m_i[1] - mnew1);
        float ps0 = 0.f, ps1 = 0.f;
        #pragma unroll
        for (int ni = 0; ni < 8; ni++) {
            sacc[ni][0] = __expf(sacc[ni][0] - mnew0);
            sacc[ni][1] = __expf(sacc[ni][1] - mnew0);
            sacc[ni][2] = __expf(sacc[ni][2] - mnew1);
            sacc[ni][3] = __expf(sacc[ni][3] - mnew1);
            ps0 += sacc[ni][0] + sacc[ni][1];
            ps1 += sacc[ni][2] + sacc[ni][3];
        }
        #pragma unroll
        for (int off = 1; off < 4; off <<= 1) {
            ps0 += __shfl_xor_sync(0xffffffffu, ps0, off);
            ps1 += __shfl_xor_sync(0xffffffffu, ps1, off);
        }
        l_i[0] = l_i[0] * al0 + ps0;  m_i[0] = mnew0;
        l_i[1] = l_i[1] * al1 + ps1;  m_i[1] = mnew1;
        #pragma unroll
        for (int ni = 0; ni < 8; ni++) {
            oacc[ni][0] *= al0; oacc[ni][1] *= al0;
            oacc[ni][2] *= al1; oacc[ni][3] *= al1;
        }

        // ---- store P (warp-local rows) ----
        #pragma unroll
        for (int ni = 0; ni < 8; ni++) {
            *(float2*)&Ps[(r0 + quad)     * PQ + ni * 8 + 2 * tq] =
                make_float2(sacc[ni][0], sacc[ni][1]);
            *(float2*)&Ps[(r0 + quad + 8) * PQ + ni * 8 + 2 * tq] =
                make_float2(sacc[ni][2], sacc[ni][3]);
        }
        __syncwarp();

        // ---- O += P V (3xTF32) ----
        #pragma unroll
        for (int kk = 0; kk < 8; kk++) {
            const int k0 = kk * 8 + tq;
            float p0 = Ps[(r0 + quad)     * PQ + k0];
            float p1 = Ps[(r0 + quad + 8) * PQ + k0];
            float p2 = Ps[(r0 + quad)     * PQ + k0 + 4];
            float p3 = Ps[(r0 + quad + 8) * PQ + k0 + 4];
            uint32_t ph[4], pl[4];
            ph[0] = f2tf32(p0); pl[0] = f2tf32(p0 - __uint_as_float(ph[0]));
            ph[1] = f2tf32(p1); pl[1] = f2tf32(p1 - __uint_as_float(ph[1]));
            ph[2] = f2tf32(p2); pl[2] = f2tf32(p2 - __uint_as_float(ph[2]));
            ph[3] = f2tf32(p3); pl[3] = f2tf32(p3 - __uint_as_float(ph[3]));
            const float* vb0 = Vs + (kk * 8 + tq) * PVV;
            const float* vb1 = Vs + (kk * 8 + tq + 4) * PVV;
            #pragma unroll
            for (int ni = 0; ni < 8; ni++) {
                float v0 = vb0[ni * 8 + quad];
                float v1 = vb1[ni * 8 + quad];
                uint32_t bh0 = f2tf32(v0), bl0 = f2tf32(v0 - __uint_as_float(bh0));
                uint32_t bh1 = f2tf32(v1), bl1 = f2tf32(v1 - __uint_as_float(bh1));
                mma_tf32_16x8x8(oacc[ni], pl, bh0, bh1);
                mma_tf32_16x8x8(oacc[ni], ph, bl0, bl1);
                mma_tf32_16x8x8(oacc[ni], ph, bh0, bh1);
            }
        }
        __syncwarp();   // P reads done before next iteration overwrites Ps
    }

    // ---- normalize + write to [B,S,H,HD] ----
    const int bidx = bh >> 4, h = bh & 15;
    #pragma unroll
    for (int half = 0; half < 2; half++) {
        const float inv = 1.0f / l_i[half];
        const int s = qt * 64 + r0 + quad + half * 8;
        float* dst = g_att + (((size_t)bidx * Seq + s) * Hn + h) * Hd;
        #pragma unroll
        for (int ni = 0; ni < 8; ni++) {
            float2 v = make_float2(oacc[ni][half * 2 + 0] * inv,
                                   oacc[ni][half * 2 + 1] * inv);
            *(float2*)(dst + ni * 8 + 2 * tq) = v;
        }
    }
}

// ---------------------------------------------------------------------------
extern "C" void kernel_launch(void* const* d_in, const int* in_sizes, int n_in,
                              void* d_out, int out_size)
{
    (void)in_sizes; (void)n_in; (void)out_size;
    const float* X    = (const float*)d_in[0];
    const float* Wq   = (const float*)d_in[1];
    const float* bq   = (const float*)d_in[2];
    const float* Wk   = (const float*)d_in[3];
    const float* bk   = (const float*)d_in[4];
    const float* Wv   = (const float*)d_in[5];
    const float* bv   = (const float*)d_in[6];
    const float* Wo   = (const float*)d_in[7];
    const float* bo   = (const float*)d_in[8];
    const float* comp = (const float*)d_in[9];
    float* out = (float*)d_out;

    cudaFuncSetAttribute(qkv_mma,   cudaFuncAttributeMaxDynamicSharedMemorySize, GEMM_SMEM_BYTES);
    cudaFuncSetAttribute(proj_mma,  cudaFuncAttributeMaxDynamicSharedMemorySize, GEMM_SMEM_BYTES);
    cudaFuncSetAttribute(flash_mma, cudaFuncAttributeMaxDynamicSharedMemorySize, FLASH_SMEM_BYTES);

    dim3 gQKV(Dm/128, Mrows/128, 3);     // (8, 64, 3)
    qkv_mma<<<gQKV, 256, GEMM_SMEM_BYTES>>>(X, Wq, bq, Wk, bk, Wv, bv);

    dim3 gFA(Seq/64, Bsz*Hn);            // (32, 64)
    flash_mma<<<gFA, 128, FLASH_SMEM_BYTES>>>();

    dim3 gP(Dm/128, Mrows/128);          // (8, 64)
    proj_mma<<<gP, 256, GEMM_SMEM_BYTES>>>(Wo, bo, comp, out);
}